// round 3
// baseline (speedup 1.0000x reference)
#include <cuda_runtime.h>
#include <math.h>

#define D_MODEL   1024
#define DIM_FF    4096
#define N_EXPERTS 8
#define N_TOKENS  8192
#define MAX_TILES 136                 // 16384/128 + 8 (per-expert round-up)
#define SLOTS     (MAX_TILES * 128)   // 17408

// ---------------- scratch (static device globals; no allocation) ----------------
__device__ int   g_cnt[N_EXPERTS];
__device__ int   g_cursor[N_EXPERTS];
__device__ int   g_tile_expert[MAX_TILES];
__device__ int   g_tok_e[N_TOKENS * 2];
__device__ float g_tok_w[N_TOKENS * 2];
__device__ int   g_assign_tok[SLOTS];
__device__ float g_assign_w[SLOTS];
__device__ float g_H[(size_t)SLOTS * DIM_FF];   // ~285 MB fp32 intermediate

// ---------------- helpers ----------------
__device__ __forceinline__ float to_tf32(float a) {
    unsigned u;
    asm("cvt.rna.tf32.f32 %0, %1;" : "=r"(u) : "f"(a));
    return __uint_as_float(u);
}
__device__ __forceinline__ float4 tf4(float4 v) {
    return make_float4(to_tf32(v.x), to_tf32(v.y), to_tf32(v.z), to_tf32(v.w));
}
__device__ __forceinline__ float gelu_exact(float v) {
    return 0.5f * v * (1.0f + erff(v * 0.70710678118654752f));
}
__device__ __forceinline__ void mma_tf32(float* c, const unsigned* a, const unsigned* b) {
    asm volatile(
        "mma.sync.aligned.m16n8k8.row.col.f32.tf32.tf32.f32 "
        "{%0,%1,%2,%3}, {%4,%5,%6,%7}, {%8,%9}, {%0,%1,%2,%3};\n"
        : "+f"(c[0]), "+f"(c[1]), "+f"(c[2]), "+f"(c[3])
        : "r"(a[0]), "r"(a[1]), "r"(a[2]), "r"(a[3]), "r"(b[0]), "r"(b[1]));
}

// ---------------- routing ----------------
__global__ void init_kernel() {
    int idx = blockIdx.x * blockDim.x + threadIdx.x;
    if (idx < SLOTS) g_assign_tok[idx] = -1;
    if (idx < N_EXPERTS) g_cnt[idx] = 0;
}

__global__ void gate_kernel(const float* __restrict__ x,
                            const float* __restrict__ Wg,
                            const float* __restrict__ bg) {
    int warp = threadIdx.x >> 5, lane = threadIdx.x & 31;
    int tok = blockIdx.x * 8 + warp;
    float acc[8];
#pragma unroll
    for (int e = 0; e < 8; e++) acc[e] = 0.f;
    const float* xr = x + (size_t)tok * D_MODEL;
    for (int d = lane; d < D_MODEL; d += 32) {
        float xv = xr[d];
        const float4* w4 = reinterpret_cast<const float4*>(Wg + d * 8);
        float4 wa = w4[0], wb = w4[1];
        acc[0] += xv * wa.x; acc[1] += xv * wa.y; acc[2] += xv * wa.z; acc[3] += xv * wa.w;
        acc[4] += xv * wb.x; acc[5] += xv * wb.y; acc[6] += xv * wb.z; acc[7] += xv * wb.w;
    }
#pragma unroll
    for (int e = 0; e < 8; e++) {
#pragma unroll
        for (int off = 16; off > 0; off >>= 1)
            acc[e] += __shfl_xor_sync(0xffffffffu, acc[e], off);
    }
    if (lane == 0) {
        float p[8];
        float mx = -1e30f;
#pragma unroll
        for (int e = 0; e < 8; e++) { p[e] = acc[e] + bg[e]; mx = fmaxf(mx, p[e]); }
        float s = 0.f;
#pragma unroll
        for (int e = 0; e < 8; e++) { p[e] = expf(p[e] - mx); s += p[e]; }
        float inv = 1.f / s;
#pragma unroll
        for (int e = 0; e < 8; e++) p[e] *= inv;
        int e0 = 0;
#pragma unroll
        for (int e = 1; e < 8; e++) if (p[e] > p[e0]) e0 = e;
        int e1 = (e0 == 0) ? 1 : 0;
#pragma unroll
        for (int e = 0; e < 8; e++) if (e != e1 && e != e0 && p[e] > p[e1]) e1 = e;
        float denom = p[e0] + p[e1] + 1e-9f;
        g_tok_e[2 * tok] = e0;     g_tok_e[2 * tok + 1] = e1;
        g_tok_w[2 * tok] = p[e0] / denom;
        g_tok_w[2 * tok + 1] = p[e1] / denom;
        atomicAdd(&g_cnt[e0], 1);
        atomicAdd(&g_cnt[e1], 1);
    }
}

__global__ void plan_kernel() {
    if (threadIdx.x == 0 && blockIdx.x == 0) {
        int ts = 0;
        for (int e = 0; e < N_EXPERTS; e++) {
            int nt = (g_cnt[e] + 127) >> 7;
            g_cursor[e] = ts * 128;
            for (int i = 0; i < nt; i++) g_tile_expert[ts + i] = e;
            ts += nt;
        }
        for (int t = ts; t < MAX_TILES; t++) g_tile_expert[t] = -1;
    }
}

__global__ void scatter_kernel() {
    int tok = blockIdx.x * blockDim.x + threadIdx.x;
    if (tok >= N_TOKENS) return;
#pragma unroll
    for (int k = 0; k < 2; k++) {
        int e = g_tok_e[2 * tok + k];
        int pos = atomicAdd(&g_cursor[e], 1);
        g_assign_tok[pos] = tok;
        g_assign_w[pos] = g_tok_w[2 * tok + k];
    }
}

__global__ void zero_out_kernel(float4* out, int n4) {
    int i = blockIdx.x * blockDim.x + threadIdx.x;
    int stride = gridDim.x * blockDim.x;
    float4 z = make_float4(0.f, 0.f, 0.f, 0.f);
    for (; i < n4; i += stride) out[i] = z;
}

// ---------------- GEMM1: H = gelu(gather(x) @ W1[e] + b1[e]) ----------------
#define STS_STAGE(s)                                   \
    do {                                               \
        *(float4*)&As[s][ra0][ca] = tf4(pa0);          \
        *(float4*)&As[s][ra1][ca] = tf4(pa1);          \
        *(float4*)&Bs[s][kb0][cb] = tf4(pb0);          \
        *(float4*)&Bs[s][kb1][cb] = tf4(pb1);          \
    } while (0)

__global__ __launch_bounds__(256) void moe_gemm1(const float* __restrict__ x,
                                                 const float* __restrict__ W1,
                                                 const float* __restrict__ b1) {
    const int mt = blockIdx.y;
    const int e = g_tile_expert[mt];
    if (e < 0) return;
    const int n0 = blockIdx.x << 7;

    __shared__ float As[2][128][20];
    __shared__ float Bs[2][16][136];
    __shared__ int toks[128];

    const int tid = threadIdx.x;
    const int lane = tid & 31, warp = tid >> 5;
    const int g = lane >> 2, t4 = lane & 3;
    const int wm = (warp & 3) << 5;   // 0,32,64,96
    const int wn = (warp >> 2) << 6;  // 0,64

    if (tid < 128) toks[tid] = g_assign_tok[(mt << 7) + tid];
    __syncthreads();

    const float* Bsrc = W1 + (size_t)e * D_MODEL * DIM_FF + n0;

    const int ra0 = tid >> 2, ra1 = ra0 + 64;
    const int ca = (tid & 3) << 2;
    const int kb0 = tid >> 5, kb1 = kb0 + 8;
    const int cb = (tid & 31) << 2;

    const int tokA0 = toks[ra0];
    const int tokA1 = toks[ra1];
    const float* xA0 = (tokA0 >= 0) ? (x + (size_t)tokA0 * D_MODEL + ca) : (const float*)0;
    const float* xA1 = (tokA1 >= 0) ? (x + (size_t)tokA1 * D_MODEL + ca) : (const float*)0;

    float acc[2][8][4];
#pragma unroll
    for (int i = 0; i < 2; i++)
#pragma unroll
        for (int j = 0; j < 8; j++)
#pragma unroll
            for (int k = 0; k < 4; k++) acc[i][j][k] = 0.f;

    const float4 z4 = make_float4(0.f, 0.f, 0.f, 0.f);
    float4 pa0, pa1, pb0, pb1;
    pa0 = xA0 ? *(const float4*)(xA0) : z4;
    pa1 = xA1 ? *(const float4*)(xA1) : z4;
    pb0 = *(const float4*)(Bsrc + (size_t)kb0 * DIM_FF + cb);
    pb1 = *(const float4*)(Bsrc + (size_t)kb1 * DIM_FF + cb);
    STS_STAGE(0);
    __syncthreads();

    const int KT = D_MODEL / 16;
    for (int kt = 0; kt < KT; kt++) {
        const int s = kt & 1;
        if (kt + 1 < KT) {
            const int k0 = (kt + 1) << 4;
            pa0 = xA0 ? *(const float4*)(xA0 + k0) : z4;
            pa1 = xA1 ? *(const float4*)(xA1 + k0) : z4;
            pb0 = *(const float4*)(Bsrc + (size_t)(k0 + kb0) * DIM_FF + cb);
            pb1 = *(const float4*)(Bsrc + (size_t)(k0 + kb1) * DIM_FF + cb);
        }
#pragma unroll
        for (int ks = 0; ks < 2; ks++) {
            const int kb = ks << 3;
            unsigned af[2][4], bf[8][2];
#pragma unroll
            for (int i = 0; i < 2; i++) {
                int r = wm + (i << 4) + g;
                af[i][0] = __float_as_uint(As[s][r][kb + t4]);
                af[i][1] = __float_as_uint(As[s][r + 8][kb + t4]);
                af[i][2] = __float_as_uint(As[s][r][kb + t4 + 4]);
                af[i][3] = __float_as_uint(As[s][r + 8][kb + t4 + 4]);
            }
#pragma unroll
            for (int j = 0; j < 8; j++) {
                int c = wn + (j << 3) + g;
                bf[j][0] = __float_as_uint(Bs[s][kb + t4][c]);
                bf[j][1] = __float_as_uint(Bs[s][kb + t4 + 4][c]);
            }
#pragma unroll
            for (int i = 0; i < 2; i++)
#pragma unroll
                for (int j = 0; j < 8; j++) mma_tf32(acc[i][j], af[i], bf[j]);
        }
        __syncthreads();
        if (kt + 1 < KT) {
            STS_STAGE((kt + 1) & 1);
            __syncthreads();
        }
    }

    const float* b1e = b1 + e * DIM_FF + n0;
#pragma unroll
    for (int i = 0; i < 2; i++) {
        int rl = wm + (i << 4) + g;
        size_t row0 = (size_t)((mt << 7) + rl);
#pragma unroll
        for (int j = 0; j < 8; j++) {
            int c = wn + (j << 3) + (t4 << 1);
            float bb0 = b1e[c], bb1 = b1e[c + 1];
            float2 v0, v1;
            v0.x = gelu_exact(acc[i][j][0] + bb0);
            v0.y = gelu_exact(acc[i][j][1] + bb1);
            v1.x = gelu_exact(acc[i][j][2] + bb0);
            v1.y = gelu_exact(acc[i][j][3] + bb1);
            *(float2*)&g_H[row0 * DIM_FF + n0 + c] = v0;
            *(float2*)&g_H[(row0 + 8) * DIM_FF + n0 + c] = v1;
        }
    }
}

// ---------------- GEMM2: out += w * (H @ W2[e] + b2[e]) scattered ----------------
__global__ __launch_bounds__(256) void moe_gemm2(const float* __restrict__ W2,
                                                 const float* __restrict__ b2,
                                                 float* __restrict__ out) {
    const int mt = blockIdx.y;
    const int e = g_tile_expert[mt];
    if (e < 0) return;
    const int n0 = blockIdx.x << 7;

    __shared__ float As[2][128][20];
    __shared__ float Bs[2][16][136];
    __shared__ int toks[128];
    __shared__ float ws[128];

    const int tid = threadIdx.x;
    const int lane = tid & 31, warp = tid >> 5;
    const int g = lane >> 2, t4 = lane & 3;
    const int wm = (warp & 3) << 5;
    const int wn = (warp >> 2) << 6;

    if (tid < 128) {
        toks[tid] = g_assign_tok[(mt << 7) + tid];
        ws[tid] = g_assign_w[(mt << 7) + tid];
    }
    __syncthreads();

    const float* Asrc = g_H + (size_t)(mt << 7) * DIM_FF;
    const float* Bsrc = W2 + (size_t)e * DIM_FF * D_MODEL + n0;

    const int ra0 = tid >> 2, ra1 = ra0 + 64;
    const int ca = (tid & 3) << 2;
    const int kb0 = tid >> 5, kb1 = kb0 + 8;
    const int cb = (tid & 31) << 2;

    float acc[2][8][4];
#pragma unroll
    for (int i = 0; i < 2; i++)
#pragma unroll
        for (int j = 0; j < 8; j++)
#pragma unroll
            for (int k = 0; k < 4; k++) acc[i][j][k] = 0.f;

    float4 pa0, pa1, pb0, pb1;
    pa0 = *(const float4*)(Asrc + (size_t)ra0 * DIM_FF + ca);
    pa1 = *(const float4*)(Asrc + (size_t)ra1 * DIM_FF + ca);
    pb0 = *(const float4*)(Bsrc + (size_t)kb0 * D_MODEL + cb);
    pb1 = *(const float4*)(Bsrc + (size_t)kb1 * D_MODEL + cb);
    STS_STAGE(0);
    __syncthreads();

    const int KT = DIM_FF / 16;
    for (int kt = 0; kt < KT; kt++) {
        const int s = kt & 1;
        if (kt + 1 < KT) {
            const int k0 = (kt + 1) << 4;
            pa0 = *(const float4*)(Asrc + (size_t)ra0 * DIM_FF + k0 + ca);
            pa1 = *(const float4*)(Asrc + (size_t)ra1 * DIM_FF + k0 + ca);
            pb0 = *(const float4*)(Bsrc + (size_t)(k0 + kb0) * D_MODEL + cb);
            pb1 = *(const float4*)(Bsrc + (size_t)(k0 + kb1) * D_MODEL + cb);
        }
#pragma unroll
        for (int ks = 0; ks < 2; ks++) {
            const int kb = ks << 3;
            unsigned af[2][4], bf[8][2];
#pragma unroll
            for (int i = 0; i < 2; i++) {
                int r = wm + (i << 4) + g;
                af[i][0] = __float_as_uint(As[s][r][kb + t4]);
                af[i][1] = __float_as_uint(As[s][r + 8][kb + t4]);
                af[i][2] = __float_as_uint(As[s][r][kb + t4 + 4]);
                af[i][3] = __float_as_uint(As[s][r + 8][kb + t4 + 4]);
            }
#pragma unroll
            for (int j = 0; j < 8; j++) {
                int c = wn + (j << 3) + g;
                bf[j][0] = __float_as_uint(Bs[s][kb + t4][c]);
                bf[j][1] = __float_as_uint(Bs[s][kb + t4 + 4][c]);
            }
#pragma unroll
            for (int i = 0; i < 2; i++)
#pragma unroll
                for (int j = 0; j < 8; j++) mma_tf32(acc[i][j], af[i], bf[j]);
        }
        __syncthreads();
        if (kt + 1 < KT) {
            STS_STAGE((kt + 1) & 1);
            __syncthreads();
        }
    }

    const float* b2e = b2 + e * D_MODEL + n0;
#pragma unroll
    for (int i = 0; i < 2; i++) {
        int rl = wm + (i << 4) + g;
        int t0 = toks[rl], t1 = toks[rl + 8];
        float w0 = ws[rl], w1 = ws[rl + 8];
#pragma unroll
        for (int j = 0; j < 8; j++) {
            int c = wn + (j << 3) + (t4 << 1);
            float bb0 = b2e[c], bb1 = b2e[c + 1];
            if (t0 >= 0) {
                atomicAdd(&out[(size_t)t0 * D_MODEL + n0 + c],     w0 * (acc[i][j][0] + bb0));
                atomicAdd(&out[(size_t)t0 * D_MODEL + n0 + c + 1], w0 * (acc[i][j][1] + bb1));
            }
            if (t1 >= 0) {
                atomicAdd(&out[(size_t)t1 * D_MODEL + n0 + c],     w1 * (acc[i][j][2] + bb0));
                atomicAdd(&out[(size_t)t1 * D_MODEL + n0 + c + 1], w1 * (acc[i][j][3] + bb1));
            }
        }
    }
}

// ---------------- launcher ----------------
extern "C" void kernel_launch(void* const* d_in, const int* in_sizes, int n_in,
                              void* d_out, int out_size) {
    const float* x  = (const float*)d_in[0];
    const float* Wg = (const float*)d_in[1];
    const float* bg = (const float*)d_in[2];
    const float* W1 = (const float*)d_in[3];
    const float* b1 = (const float*)d_in[4];
    const float* W2 = (const float*)d_in[5];
    const float* b2 = (const float*)d_in[6];
    float* out = (float*)d_out;
    (void)in_sizes; (void)n_in;

    init_kernel<<<(SLOTS + 255) / 256, 256>>>();
    gate_kernel<<<N_TOKENS / 8, 256>>>(x, Wg, bg);
    plan_kernel<<<1, 32>>>();
    scatter_kernel<<<N_TOKENS / 256, 256>>>();
    zero_out_kernel<<<1024, 256>>>((float4*)d_out, out_size / 4);
    moe_gemm1<<<dim3(DIM_FF / 128, MAX_TILES), 256>>>(x, W1, b1);
    moe_gemm2<<<dim3(D_MODEL / 128, MAX_TILES), 256>>>(W2, b2, out);
}